// round 7
// baseline (speedup 1.0000x reference)
#include <cuda_runtime.h>
#include <math.h>

#define PI_F 3.14159265358979323846f

__device__ float g_coef[256 * 6];

__global__ void prep_kernel(const float* __restrict__ theta, int B,
                            float sW, float sH) {
    int i = blockIdx.x * blockDim.x + threadIdx.x;
    if (i >= B * 6) return;
    int rc = i % 6;
    int r = rc / 3;
    const float m1[6] = {1.0f,  PI_F,        0.2f,  PI_F,        1.0f, 0.2f};
    const float m2[6] = {0.5f, -PI_F * 0.5f, -0.1f, -PI_F * 0.5f, 0.5f, -0.1f};
    float v = fmaf(theta[i], m1[rc], m2[rc]);
    g_coef[i] = v * (r == 0 ? sW : sH);
}

// Block = 128 threads covering a 32x32 output tile.
// Warp covers 32x8 (8 x-groups * 4 y-lanes); each thread owns a 4x2 rect.
__global__ __launch_bounds__(128, 8)
void stn_kernel(const float* __restrict__ img, float* __restrict__ out,
                int H, int W, float inv) {
    const int b = blockIdx.z;
    const int tx = threadIdx.x;          // 0..31
    const int ty = threadIdx.y;          // 0..3 (warp id)
    const int lx = tx & 7;
    const int ly = tx >> 3;

    const int wpix = blockIdx.x * 32 + lx * 4;          // 4 x pixels
    const int hpix = blockIdx.y * 32 + ty * 8 + ly * 2; // 2 y rows
    if (hpix >= H || wpix >= W) return;

    const float c0 = g_coef[b * 6 + 0];
    const float c1 = g_coef[b * 6 + 1];
    const float c2 = g_coef[b * 6 + 2];
    const float c3 = g_coef[b * 6 + 3];
    const float c4 = g_coef[b * 6 + 4];
    const float c5 = g_coef[b * 6 + 5];

    const float Wm1 = (float)(W - 1);
    const float Hm1 = (float)(H - 1);
    const float fw = (float)wpix;
    const float xnA = fw * inv;
    const float xnB = (fw + 3.0f) * inv;

    // Per-row affine bases (same arithmetic as reference per-pixel path).
    float bxr[2], byr[2];
#pragma unroll
    for (int r = 0; r < 2; r++) {
        const float yn = (float)(hpix + r) * inv;
        bxr[r] = fmaf(c1, yn, c2);
        byr[r] = fmaf(c4, yn, c5);
    }

    // Classify the 4x2 rect via its 4 corners (xs/ys linear in w and h).
    bool allin = true, outL = true, outR = true, outT = true, outBo = true;
#pragma unroll
    for (int r = 0; r < 2; r++) {
        const float xA = fmaf(c0, xnA, bxr[r]), xB = fmaf(c0, xnB, bxr[r]);
        const float yA = fmaf(c3, xnA, byr[r]), yB = fmaf(c3, xnB, byr[r]);
        allin &= (xA >= 0.0f) & (xB >= 0.0f) & (xA < Wm1) & (xB < Wm1) &
                 (yA >= 0.0f) & (yB >= 0.0f) & (yA < Hm1) & (yB < Hm1);
        outL &= (xA < 0.0f) & (xB < 0.0f);
        outR &= (xA >= Wm1) & (xB >= Wm1);
        outT &= (yA < 0.0f) & (yB < 0.0f);
        outBo &= (yA >= Hm1) & (yB >= Hm1);
    }
    const bool allout = outL | outR | outT | outBo;

    const float* __restrict__ imgb = img + (size_t)b * H * W;
    float* __restrict__ op0 = out + (size_t)b * H * W + (size_t)hpix * W + wpix;

    if (allout) {
        const float4 z = make_float4(0.f, 0.f, 0.f, 0.f);
        __stcs(reinterpret_cast<float4*>(op0), z);
        __stcs(reinterpret_cast<float4*>(op0 + W), z);
        return;
    }

    if (allin) {
        // Phase 1: indices only (minimal live state during load flight).
        int idx[2][4];
#pragma unroll
        for (int r = 0; r < 2; r++) {
#pragma unroll
            for (int i = 0; i < 4; i++) {
                const float xn = (fw + (float)i) * inv;
                const float xs = fmaf(c0, xn, bxr[r]);
                const float ys = fmaf(c3, xn, byr[r]);
                idx[r][i] = (int)ys * W + (int)xs;   // xs,ys >= 0 guaranteed
            }
        }
        // Phase 2: all 32 gathers issued back-to-back.
        float Ia[2][4], Ib[2][4], Ic[2][4], Id[2][4];
#pragma unroll
        for (int r = 0; r < 2; r++) {
#pragma unroll
            for (int i = 0; i < 4; i++) {
                Ia[r][i] = __ldg(imgb + idx[r][i]);
                Ic[r][i] = __ldg(imgb + idx[r][i] + 1);
                Ib[r][i] = __ldg(imgb + idx[r][i] + W);
                Id[r][i] = __ldg(imgb + idx[r][i] + W + 1);
            }
        }
        // Phase 3: recompute weights (executes under load latency), combine.
#pragma unroll
        for (int r = 0; r < 2; r++) {
            float4 res;
            float* rp = &res.x;
#pragma unroll
            for (int i = 0; i < 4; i++) {
                const float xn = (fw + (float)i) * inv;
                const float xs = fmaf(c0, xn, bxr[r]);
                const float ys = fmaf(c3, xn, byr[r]);
                const float x0f = floorf(xs);   // == (float)(int)xs for xs>=0
                const float y0f = floorf(ys);
                const float wx0 = xs - x0f;
                const float wx1 = (x0f + 1.0f) - xs;
                const float wy0 = ys - y0f;
                const float wy1 = (y0f + 1.0f) - ys;
                rp[i] = wy1 * fmaf(wx1, Ia[r][i], wx0 * Ic[r][i]) +
                        wy0 * fmaf(wx1, Ib[r][i], wx0 * Id[r][i]);
            }
            __stcs(reinterpret_cast<float4*>(op0 + r * W), res);
        }
        return;
    }

    // Mixed rect: per-pixel branch, identical predicate arithmetic.
#pragma unroll
    for (int r = 0; r < 2; r++) {
        const float bx = bxr[r], by = byr[r];
        float res[4];
#pragma unroll
        for (int p = 0; p < 4; p++) {
            const float xn = (fw + (float)p) * inv;
            const float xs = fmaf(c0, xn, bx);
            const float ys = fmaf(c3, xn, by);
            float v = 0.0f;
            if (xs >= 0.0f && xs < Wm1 && ys >= 0.0f && ys < Hm1) {
                const int x0 = (int)xs;
                const int y0 = (int)ys;
                const float x0f = (float)x0;
                const float y0f = (float)y0;
                const float fx0 = xs - x0f;
                const float fx1 = (x0f + 1.0f) - xs;
                const float fy0 = ys - y0f;
                const float fy1 = (y0f + 1.0f) - ys;
                const int idx = y0 * W + x0;
                const float Ia = __ldg(imgb + idx);
                const float Ic = __ldg(imgb + idx + 1);
                const float Ib = __ldg(imgb + idx + W);
                const float Id = __ldg(imgb + idx + W + 1);
                v = fy1 * fmaf(fx1, Ia, fx0 * Ic) +
                    fy0 * fmaf(fx1, Ib, fx0 * Id);
            }
            res[p] = v;
        }
        __stcs(reinterpret_cast<float4*>(op0 + r * W),
               make_float4(res[0], res[1], res[2], res[3]));
    }
}

extern "C" void kernel_launch(void* const* d_in, const int* in_sizes, int n_in,
                              void* d_out, int out_size) {
    const float* img   = (const float*)d_in[0];
    const float* theta = (const float*)d_in[1];

    const int B = in_sizes[1] / 6;
    const long long hw = (long long)in_sizes[0] / B;
    const int W = (int)(sqrt((double)hw) + 0.5);
    const int H = (int)(hw / W);

    prep_kernel<<<(B * 6 + 127) / 128, 128>>>(theta, B, (float)(W - 1), (float)(H - 1));

    dim3 blk(32, 4, 1);
    dim3 grd((W + 31) / 32, (H + 31) / 32, B);
    stn_kernel<<<grd, blk>>>(img, (float*)d_out, H, W, 1.0f / (float)(W - 1));
}